// round 15
// baseline (speedup 1.0000x reference)
#include <cuda_runtime.h>
#include <cuda_fp16.h>
#include <cstdint>

#define NB 4
#define NN 4096
#define LOG2E 1.4426950408889634f

// ---------------- scratch (__device__ globals; no allocation) ----------------
__device__ __align__(256) __half  g_Qh[NB * NN * 8];     // [b][n][8], pre-scaled by log2e
__device__ __align__(256) __half  g_Kh[NB * NN * 8];     // [b][n][8]
// V in e4m3, pre-arranged per 128-key tile in mma B-fragment layout:
// [b][tile][kq(4)][nt(8)][lane(32)][8B]  (8192 B per tile)
__device__ __align__(256) uint8_t g_V8[NB * NN * 64];

// ---------------- helpers ----------------
__device__ __forceinline__ uint32_t smem_u32(const void* p) {
    uint32_t a;
    asm("{ .reg .u64 t; cvta.to.shared.u64 t, %1; cvt.u32.u64 %0, t; }" : "=r"(a) : "l"(p));
    return a;
}
#define CP_ASYNC16(dst, src) \
    asm volatile("cp.async.cg.shared.global [%0], [%1], 16;" :: "r"(dst), "l"(src) : "memory")
#define CP_COMMIT() asm volatile("cp.async.commit_group;" ::: "memory")
#define CP_WAIT0()  asm volatile("cp.async.wait_group 0;" ::: "memory")

#define LDSM_X4(r0, r1, r2, r3, a) \
    asm volatile("ldmatrix.sync.aligned.m8n8.x4.shared.b16 {%0,%1,%2,%3}, [%4];" \
                 : "=r"(r0), "=r"(r1), "=r"(r2), "=r"(r3) : "r"(a))

// S(16x8,f16) = Q(16x8,f16) @ K^T ; C = 0
__device__ __forceinline__ void mma16808h(uint32_t* d, uint32_t a0, uint32_t a1, uint32_t b0) {
    uint32_t z = 0;
    asm volatile("mma.sync.aligned.m16n8k8.row.col.f16.f16.f16.f16 "
                 "{%0,%1}, {%2,%3}, {%4}, {%5,%5};"
                 : "=r"(d[0]), "=r"(d[1]) : "r"(a0), "r"(a1), "r"(b0), "r"(z));
}
// O(16x8,f32) += P(16x32,e4m3) @ V(32x8,e4m3)
__device__ __forceinline__ void mma_fp8(float* d, const uint32_t* a, uint32_t b0, uint32_t b1) {
    asm volatile("mma.sync.aligned.m16n8k32.row.col.f32.e4m3.e4m3.f32 "
                 "{%0,%1,%2,%3}, {%4,%5,%6,%7}, {%8,%9}, {%0,%1,%2,%3};"
                 : "+f"(d[0]), "+f"(d[1]), "+f"(d[2]), "+f"(d[3])
                 : "r"(a[0]), "r"(a[1]), "r"(a[2]), "r"(a[3]), "r"(b0), "r"(b1));
}
#define EX2H2(r) asm volatile("ex2.approx.f16x2 %0, %0;" : "+r"(r))
__device__ __forceinline__ uint32_t hadd2u(uint32_t a, uint32_t b) {
    uint32_t d; asm("add.rn.f16x2 %0, %1, %2;" : "=r"(d) : "r"(a), "r"(b)); return d;
}
__device__ __forceinline__ float h2sumf(uint32_t r) {
    __half2 h = *reinterpret_cast<__half2*>(&r);
    return __low2float(h) + __high2float(h);
}
// two f16x2 regs -> one fp8x4 reg (bytes: lo.lo, lo.hi, hi.lo, hi.hi)
__device__ __forceinline__ uint32_t pk_e4m3(uint32_t plo, uint32_t phi) {
    unsigned short lo, hi;
    asm("cvt.rn.satfinite.e4m3x2.f16x2 %0, %1;" : "=h"(lo) : "r"(plo));
    asm("cvt.rn.satfinite.e4m3x2.f16x2 %0, %1;" : "=h"(hi) : "r"(phi));
    return (uint32_t)lo | ((uint32_t)hi << 16);
}
__device__ __forceinline__ uint8_t f32_e4m3(float v) {
    unsigned short r;
    asm("cvt.rn.satfinite.e4m3x2.f32 %0, %1, %2;" : "=h"(r) : "f"(v), "f"(v));
    return (uint8_t)(r & 0xFFu);
}

// ---------------------------------------------------------------------------
// Kernel 1: fused QKV projections. Q/K f16; V e4m3 scattered into the
// mma-B-fragment layout (key permutation pi baked in), coalesced copy-out.
// ---------------------------------------------------------------------------
__global__ __launch_bounds__(256) void prep_kernel(
    const float* __restrict__ x,
    const float* __restrict__ Wq, const float* __restrict__ bq,
    const float* __restrict__ Wk, const float* __restrict__ bk,
    const float* __restrict__ Wv, const float* __restrict__ bv)
{
    __shared__ __align__(16) float xs[64 * 64];
    __shared__ __align__(16) float ws[80 * 64];   // weights; reused as output staging
    __shared__ float bs[80];

    const int t  = threadIdx.x;
    const int b  = blockIdx.y;
    const int n0 = blockIdx.x * 64;

    for (int lin = t; lin < 80 * 64; lin += 256) {
        int o = lin >> 6, c = lin & 63;
        float w;
        if (o < 8)       w = Wq[o * 64 + c] * LOG2E;
        else if (o < 16) w = Wk[(o - 8) * 64 + c];
        else             w = Wv[(o - 16) * 64 + c];
        ws[o * 64 + c] = w;
    }
    if (t < 80) {
        float bb;
        if (t < 8)       bb = bq[t] * LOG2E;
        else if (t < 16) bb = bk[t - 8];
        else             bb = bv[t - 16];
        bs[t] = bb;
    }
    for (int lin = t; lin < 64 * 64; lin += 256) {
        int c = lin >> 6, i = lin & 63;
        xs[c * 64 + i] = x[(b * 64 + c) * NN + n0 + i];
    }
    __syncthreads();

    const int tx = t & 63;
    const int ty = t >> 6;

    float acc[20];
#pragma unroll
    for (int i = 0; i < 20; i++) acc[i] = 0.f;
#pragma unroll
    for (int c = 0; c < 64; c++) {
        float xv = xs[c * 64 + tx];
#pragma unroll
        for (int oo = 0; oo < 20; oo++)
            acc[oo] += ws[(ty * 20 + oo) * 64 + c] * xv;
    }
    float bias[20];
#pragma unroll
    for (int oo = 0; oo < 20; oo++) bias[oo] = bs[ty * 20 + oo];

    __syncthreads();   // done reading ws -> reuse as staging

    // staging: SQ [pix][8ch] f16 @0 (1KB) | SK @1024 (1KB) | V8 bytes @2048 (4KB)
    char* stage = (char*)ws;
    // pi bookkeeping for this pixel (constant per thread)
    const int krel = tx, w32 = krel & 31, kqloc = krel >> 5;
    const int wlo = w32 & 15, h16 = w32 >> 4;
    int j = (wlo < 8) ? (4 * (wlo >> 1) + (wlo & 1))
                      : (4 * ((wlo - 8) >> 1) + 2 + (wlo & 1));
    j += h16 << 4;
    const int cc = (j >> 2) & 3, ssb = j & 3, hf = j >> 4;

#pragma unroll
    for (int oo = 0; oo < 20; oo++) {
        int o = ty * 20 + oo;
        float v = acc[oo] + bias[oo];
        if (o < 8)
            *(__half*)(stage + tx * 16 + o * 2) = __float2half(v);
        else if (o < 16)
            *(__half*)(stage + 1024 + tx * 16 + (o - 8) * 2) = __float2half(v);
        else {
            int ch = o - 16;
            int lanep = (ch & 7) * 4 + cc, ntv = ch >> 3;
            stage[2048 + kqloc * 2048 + ntv * 256 + lanep * 8 + hf * 4 + ssb] =
                (char)f32_e4m3(v);
        }
    }
    __syncthreads();

    if (t < 64) {
        *(uint4*)(g_Qh + ((size_t)b * NN + n0 + t) * 8) = *(const uint4*)(stage + t * 16);
    } else if (t < 128) {
        int i = t - 64;
        *(uint4*)(g_Kh + ((size_t)b * NN + n0 + i) * 8) = *(const uint4*)(stage + 1024 + i * 16);
    }
    // V8: 4KB contiguous in gmem (this CTA covers 2 kq-groups of tile n0>>7)
    {
        uint4 v = *(const uint4*)(stage + 2048 + t * 16);
        *(uint4*)(g_V8 + (size_t)b * 262144 + (size_t)(n0 >> 7) * 8192
                  + (size_t)((n0 >> 5) & 3) * 2048 + (size_t)t * 16) = v;
    }
}

// ---------------------------------------------------------------------------
// Kernel 2: flash attention. MMA1 f16 (k=8), MMA2 fp8 e4m3 (k=32, permuted
// keys; P converted in registers, V pre-laid-out -> single LDS.64 per nt).
// CTA = 64 queries, 8 warps (rowgrp x key-quarter), double-buffered cp.async.
// ---------------------------------------------------------------------------
#define SM_K0 0u
#define SM_K1 2048u
#define SM_V0 4096u
#define SM_V1 12288u
#define SM_L  32768u
#define U_BYTES 36864

__global__ __launch_bounds__(256, 2) void attn_kernel(
    const float* __restrict__ x,
    const float* __restrict__ gamma_p,
    float* __restrict__ out)
{
    __shared__ __align__(128) __half sQ[64 * 8];
    __shared__ __align__(1024) unsigned char U[U_BYTES];

    const int t      = threadIdx.x;
    const int lane   = t & 31;
    const int w      = t >> 5;
    const int rowgrp = w >> 2;          // 0,1 -> rows [32*rowgrp, +32)
    const int kq     = w & 3;           // 32-key quarter of each 128-key tile
    const int b      = blockIdx.y;
    const int q0     = blockIdx.x * 64;

    const uint32_t sbQ = smem_u32(sQ);
    const uint32_t sbU = smem_u32(U);

    cudaGridDependencySynchronize();    // PDL: prep outputs ready

    // initial loads: Q + tile 0
    if (t < 64)
        CP_ASYNC16(sbQ + (uint32_t)t * 16u, (const char*)(g_Qh + ((size_t)b * NN + q0 + t) * 8));
    if (t < 128)
        CP_ASYNC16(sbU + SM_K0 + (uint32_t)t * 16u, (const char*)(g_Kh + ((size_t)b * NN + t) * 8));
#pragma unroll
    for (int i = 0; i < 2; i++) {       // V: 512 x 16B linear
        int cid = t + i * 256;
        CP_ASYNC16(sbU + SM_V0 + (uint32_t)cid * 16u,
                   (const char*)(g_V8 + (size_t)b * 262144 + (size_t)cid * 16));
    }
    CP_COMMIT();

    float o0[32], o1[32];               // [nt*4+i] f32 accumulators per rowfrag
#pragma unroll
    for (int i = 0; i < 32; i++) { o0[i] = 0.f; o1[i] = 0.f; }
    float lacc[4] = {0.f, 0.f, 0.f, 0.f};
    uint32_t qa[4];

    CP_WAIT0();
    __syncthreads();
    LDSM_X4(qa[0], qa[1], qa[2], qa[3], sbQ + (uint32_t)(rowgrp * 32 + lane) * 16u);

    for (int it = 0; it < 32; it++) {
        if (it + 1 < 32) {              // prefetch next tile into other buffer
            const int nb = (it + 1) & 1;
            const uint32_t kdst = sbU + (nb ? SM_K1 : SM_K0);
            const uint32_t vdst = sbU + (nb ? SM_V1 : SM_V0);
            if (t < 128)
                CP_ASYNC16(kdst + (uint32_t)t * 16u,
                           (const char*)(g_Kh + ((size_t)b * NN + (it + 1) * 128 + t) * 8));
#pragma unroll
            for (int i = 0; i < 2; i++) {
                int cid = t + i * 256;
                CP_ASYNC16(vdst + (uint32_t)cid * 16u,
                           (const char*)(g_V8 + (size_t)b * 262144
                                         + (size_t)(it + 1) * 8192 + (size_t)cid * 16));
            }
            CP_COMMIT();
        }

        const uint32_t kbuf = sbU + ((it & 1) ? SM_K1 : SM_K0);
        const uint32_t vbuf = sbU + ((it & 1) ? SM_V1 : SM_V0);

        uint32_t kb[4];                 // this warp's 32-key quarter (f16 K)
        LDSM_X4(kb[0], kb[1], kb[2], kb[3], kbuf + (uint32_t)(kq * 32 + lane) * 16u);

        // ---- MMA1 + EX2 + fp8 A-frag build (two 16-key chunks) ----
        uint32_t aF0[4], aF1[4];
#pragma unroll
        for (int m = 0; m < 2; m++) {
            uint32_t p[8];
            mma16808h(p + 0, qa[0], qa[1], kb[2 * m]);
            mma16808h(p + 2, qa[0], qa[1], kb[2 * m + 1]);
            mma16808h(p + 4, qa[2], qa[3], kb[2 * m]);
            mma16808h(p + 6, qa[2], qa[3], kb[2 * m + 1]);

            EX2H2(p[0]); EX2H2(p[1]); EX2H2(p[2]); EX2H2(p[3]);
            EX2H2(p[4]); EX2H2(p[5]); EX2H2(p[6]); EX2H2(p[7]);

            lacc[0] += h2sumf(hadd2u(p[0], p[2]));
            lacc[1] += h2sumf(hadd2u(p[1], p[3]));
            lacc[2] += h2sumf(hadd2u(p[4], p[6]));
            lacc[3] += h2sumf(hadd2u(p[5], p[7]));

            aF0[2 * m + 0] = pk_e4m3(p[0], p[2]);   // row r,   k 16m..16m+15
            aF0[2 * m + 1] = pk_e4m3(p[1], p[3]);   // row r+8
            aF1[2 * m + 0] = pk_e4m3(p[4], p[6]);
            aF1[2 * m + 1] = pk_e4m3(p[5], p[7]);
        }
        // reorder to {a0,a1,a2,a3} = {r k0-15, r+8 k0-15, r k16-31, r+8 k16-31}
        // (already in that order: [0]=chunk0 r, [1]=chunk0 r+8, [2]=chunk1 r, [3]=chunk1 r+8)

        // ---- MMA2: one LDS.64 per nt, two fp8 mma ----
        const uint32_t vrow = vbuf + (uint32_t)kq * 2048u + (uint32_t)lane * 8u;
#pragma unroll
        for (int nt = 0; nt < 8; nt++) {
            uint32_t vb0, vb1;
            asm volatile("ld.shared.v2.b32 {%0,%1}, [%2];"
                         : "=r"(vb0), "=r"(vb1) : "r"(vrow + (uint32_t)nt * 256u));
            mma_fp8(o0 + 4 * nt, aF0, vb0, vb1);
            mma_fp8(o1 + 4 * nt, aF1, vb0, vb1);
        }

        if (it + 1 < 32) {
            CP_WAIT0();
            __syncthreads();
        }
    }

    // ---- epilogue: combine 4 key-quarters through smem (f16 staging) ----
#pragma unroll
    for (int j = 0; j < 4; j++) {
        lacc[j] += __shfl_xor_sync(0xffffffffu, lacc[j], 1);
        lacc[j] += __shfl_xor_sync(0xffffffffu, lacc[j], 2);
    }
    const float gma = __ldg(gamma_p);

    __syncthreads();            // loop reads of U done

    __half* sOp = (__half*)U;               // [kq][ch 64][q 64]
    float*  sL  = (float*)(U + SM_L);       // [kq][64]

    if ((lane & 3) == 0) {
#pragma unroll
        for (int j = 0; j < 4; j++) {
            int row = rowgrp * 32 + (j >> 1) * 16 + (j & 1) * 8 + (lane >> 2);
            sL[kq * 64 + row] = lacc[j];
        }
    }
    {
        const int r0 = rowgrp * 32 + (lane >> 2);
        const int cq = (lane & 3) * 2;
#pragma unroll
        for (int rf = 0; rf < 2; rf++) {
            const float* oo = rf ? o1 : o0;
            int rbase = r0 + rf * 16;
#pragma unroll
            for (int nt = 0; nt < 8; nt++) {
                int c0 = nt * 8 + cq;
                sOp[(kq * 64 + c0) * 64 + rbase]         = __float2half(oo[4 * nt + 0]);
                sOp[(kq * 64 + c0 + 1) * 64 + rbase]     = __float2half(oo[4 * nt + 1]);
                sOp[(kq * 64 + c0) * 64 + rbase + 8]     = __float2half(oo[4 * nt + 2]);
                sOp[(kq * 64 + c0 + 1) * 64 + rbase + 8] = __float2half(oo[4 * nt + 3]);
            }
        }
    }
    __syncthreads();

    {
        const int q = t & 63;
        const float l = sL[q] + sL[64 + q] + sL[128 + q] + sL[192 + q];
        const float inv = gma / l;
#pragma unroll
        for (int i = 0; i < 16; i++) {
            int c = (t >> 6) + 4 * i;
            float acc = (float)sOp[(0 * 64 + c) * 64 + q] + (float)sOp[(1 * 64 + c) * 64 + q]
                      + (float)sOp[(2 * 64 + c) * 64 + q] + (float)sOp[(3 * 64 + c) * 64 + q];
            size_t idx = ((size_t)b * 64 + c) * NN + q0 + q;
            out[idx] = acc * inv + x[idx];
        }
    }
}

// ---------------------------------------------------------------------------
extern "C" void kernel_launch(void* const* d_in, const int* in_sizes, int n_in,
                              void* d_out, int out_size) {
    (void)in_sizes; (void)n_in; (void)out_size;
    const float* x     = (const float*)d_in[0];
    const float* Wq    = (const float*)d_in[1];
    const float* bq    = (const float*)d_in[2];
    const float* Wk    = (const float*)d_in[3];
    const float* bk    = (const float*)d_in[4];
    const float* Wv    = (const float*)d_in[5];
    const float* bv    = (const float*)d_in[6];
    const float* gamma = (const float*)d_in[7];
    float* out = (float*)d_out;

    prep_kernel<<<dim3(64, NB), 256>>>(x, Wq, bq, Wk, bk, Wv, bv);

    cudaLaunchConfig_t cfg = {};
    cfg.gridDim  = dim3(64, NB);
    cfg.blockDim = dim3(256);
    cfg.dynamicSmemBytes = 0;
    cfg.stream = 0;
    cudaLaunchAttribute attrs[1];
    attrs[0].id = cudaLaunchAttributeProgrammaticStreamSerialization;
    attrs[0].val.programmaticStreamSerializationAllowed = 1;
    cfg.attrs = attrs;
    cfg.numAttrs = 1;
    cudaLaunchKernelEx(&cfg, attn_kernel, x, gamma, out);
}

// round 17
// speedup vs baseline: 1.1984x; 1.1984x over previous
#include <cuda_runtime.h>
#include <cuda_fp16.h>
#include <cstdint>

#define NB 4
#define NN 4096
#define LOG2E 1.4426950408889634f

// ---------------- scratch (__device__ globals; no allocation) ----------------
__device__ __align__(256) __half g_Qh[NB * NN * 8];   // [b][n][8], pre-scaled by log2e
__device__ __align__(256) __half g_Kh[NB * NN * 8];   // [b][n][8]
__device__ __align__(256) __half g_Vh[NB * NN * 64];  // [b][n][64]

// ---------------- helpers ----------------
__device__ __forceinline__ uint32_t smem_u32(const void* p) {
    uint32_t a;
    asm("{ .reg .u64 t; cvta.to.shared.u64 t, %1; cvt.u32.u64 %0, t; }" : "=r"(a) : "l"(p));
    return a;
}
__device__ __forceinline__ uint32_t swz128(uint32_t b) { return b ^ ((b >> 3) & 0x70u); }

#define CP_ASYNC16(dst, src) \
    asm volatile("cp.async.cg.shared.global [%0], [%1], 16;" :: "r"(dst), "l"(src) : "memory")
#define CP_COMMIT() asm volatile("cp.async.commit_group;" ::: "memory")
#define CP_WAIT0()  asm volatile("cp.async.wait_group 0;" ::: "memory")
#define CP_WAIT1()  asm volatile("cp.async.wait_group 1;" ::: "memory")

#define LDSM_X4(r0, r1, r2, r3, a) \
    asm volatile("ldmatrix.sync.aligned.m8n8.x4.shared.b16 {%0,%1,%2,%3}, [%4];" \
                 : "=r"(r0), "=r"(r1), "=r"(r2), "=r"(r3) : "r"(a))
#define LDSM_X4T(r0, r1, r2, r3, a) \
    asm volatile("ldmatrix.sync.aligned.m8n8.x4.trans.shared.b16 {%0,%1,%2,%3}, [%4];" \
                 : "=r"(r0), "=r"(r1), "=r"(r2), "=r"(r3) : "r"(a))

// S(16x8,f16) = Q(16x8,f16) @ K^T ; C = 0
__device__ __forceinline__ void mma16808h(uint32_t* d, uint32_t a0, uint32_t a1, uint32_t b0) {
    uint32_t z = 0;
    asm volatile("mma.sync.aligned.m16n8k8.row.col.f16.f16.f16.f16 "
                 "{%0,%1}, {%2,%3}, {%4}, {%5,%5};"
                 : "=r"(d[0]), "=r"(d[1]) : "r"(a0), "r"(a1), "r"(b0), "r"(z));
}
// O(16x8,f16) += P(16x16,f16) @ V(16x8,f16)
__device__ __forceinline__ void mma16816h(uint32_t* d, const uint32_t* a, uint32_t b0, uint32_t b1) {
    asm volatile("mma.sync.aligned.m16n8k16.row.col.f16.f16.f16.f16 "
                 "{%0,%1}, {%2,%3,%4,%5}, {%6,%7}, {%0,%1};"
                 : "+r"(d[0]), "+r"(d[1])
                 : "r"(a[0]), "r"(a[1]), "r"(a[2]), "r"(a[3]), "r"(b0), "r"(b1));
}
#define EX2H2(r) asm volatile("ex2.approx.f16x2 %0, %0;" : "+r"(r))
__device__ __forceinline__ uint32_t hadd2u(uint32_t a, uint32_t b) {
    uint32_t d; asm("add.rn.f16x2 %0, %1, %2;" : "=r"(d) : "r"(a), "r"(b)); return d;
}
__device__ __forceinline__ float h2sumf(uint32_t r) {
    __half2 h = *reinterpret_cast<__half2*>(&r);
    return __low2float(h) + __high2float(h);
}

// ---------------------------------------------------------------------------
// Kernel 1: fused QKV projections (f16 outputs, staged coalesced stores)
// ---------------------------------------------------------------------------
__global__ __launch_bounds__(256) void prep_kernel(
    const float* __restrict__ x,
    const float* __restrict__ Wq, const float* __restrict__ bq,
    const float* __restrict__ Wk, const float* __restrict__ bk,
    const float* __restrict__ Wv, const float* __restrict__ bv)
{
    __shared__ __align__(16) float xs[64 * 64];
    __shared__ __align__(16) float ws[80 * 64];   // weights; reused as output staging
    __shared__ float bs[80];

    const int t  = threadIdx.x;
    const int b  = blockIdx.y;
    const int n0 = blockIdx.x * 64;

    for (int lin = t; lin < 80 * 64; lin += 256) {
        int o = lin >> 6, c = lin & 63;
        float w;
        if (o < 8)       w = Wq[o * 64 + c] * LOG2E;
        else if (o < 16) w = Wk[(o - 8) * 64 + c];
        else             w = Wv[(o - 16) * 64 + c];
        ws[o * 64 + c] = w;
    }
    if (t < 80) {
        float bb;
        if (t < 8)       bb = bq[t] * LOG2E;
        else if (t < 16) bb = bk[t - 8];
        else             bb = bv[t - 16];
        bs[t] = bb;
    }
    for (int lin = t; lin < 64 * 64; lin += 256) {
        int c = lin >> 6, i = lin & 63;
        xs[c * 64 + i] = x[(b * 64 + c) * NN + n0 + i];
    }
    __syncthreads();

    const int tx = t & 63;
    const int ty = t >> 6;

    float acc[20];
#pragma unroll
    for (int i = 0; i < 20; i++) acc[i] = 0.f;
#pragma unroll
    for (int c = 0; c < 64; c++) {
        float xv = xs[c * 64 + tx];
#pragma unroll
        for (int oo = 0; oo < 20; oo++)
            acc[oo] += ws[(ty * 20 + oo) * 64 + c] * xv;
    }
    float bias[20];
#pragma unroll
    for (int oo = 0; oo < 20; oo++) bias[oo] = bs[ty * 20 + oo];

    __syncthreads();   // done reading ws -> reuse as staging

    char* stage = (char*)ws;
#pragma unroll
    for (int oo = 0; oo < 20; oo++) {
        int o = ty * 20 + oo;
        __half h = __float2half(acc[oo] + bias[oo]);
        if (o < 8)
            *(__half*)(stage + tx * 16 + o * 2) = h;
        else if (o < 16)
            *(__half*)(stage + 1024 + tx * 16 + (o - 8) * 2) = h;
        else
            *(__half*)(stage + 2048 + tx * 136 + (o - 16) * 2) = h;
    }
    __syncthreads();

    if (t < 64) {
        *(uint4*)(g_Qh + ((size_t)b * NN + n0 + t) * 8) = *(const uint4*)(stage + t * 16);
    } else if (t < 128) {
        int i = t - 64;
        *(uint4*)(g_Kh + ((size_t)b * NN + n0 + i) * 8) = *(const uint4*)(stage + 1024 + i * 16);
    }
#pragma unroll
    for (int i = 0; i < 4; i++) {
        int lin = t + i * 256;               // 1024 chunks of 8B
        int pix = lin >> 4, chk = lin & 15;
        *(uint2*)(g_Vh + ((size_t)b * NN + n0 + pix) * 64 + chk * 4) =
            *(const uint2*)(stage + 2048 + pix * 136 + chk * 8);
    }
}

// ---------------------------------------------------------------------------
// Kernel 2: flash attention, all-f16 mma.sync (R8 structure) with a
// 3-STAGE cp.async pipeline (CP_WAIT1) — the only change vs R8.
// CTA = 64 queries, 8 warps: rowgrp = w>>2 (32 rows), kq = w&3 (32-key
// quarter of each 128-key tile). One barrier/iter; P register-chained.
// ---------------------------------------------------------------------------
#define SM_SQ 0u
#define SM_ST 1024u
#define STAGE 18432u            // K 2KB + V 16KB per stage
#define DSMEM_BYTES 56320u      // 1KB sQ + 3 stages
#define EP_OP 1024u             // epilogue: [kq][ch 64][q 64] f16 (32KB)
#define EP_L  33792u            // float[4][64]

__global__ __launch_bounds__(256, 2) void attn_kernel(
    const float* __restrict__ x,
    const float* __restrict__ gamma_p,
    float* __restrict__ out)
{
    extern __shared__ __align__(1024) unsigned char dynsm[];

    const int t      = threadIdx.x;
    const int lane   = t & 31;
    const int w      = t >> 5;
    const int rowgrp = w >> 2;          // 0,1 -> rows [32*rowgrp, +32)
    const int kq     = w & 3;           // key quarter within each 128-key tile
    const int b      = blockIdx.y;
    const int q0     = blockIdx.x * 64;

    const uint32_t sb  = smem_u32(dynsm);
    const uint32_t sbQ = sb + SM_SQ;

    // PDL: wait for prep_kernel before touching its outputs
    cudaGridDependencySynchronize();

    // prologue: Q + tile 0 (group 0), tile 1 (group 1)
    if (t < 64)
        CP_ASYNC16(sbQ + (uint32_t)t * 16u, (const char*)(g_Qh + ((size_t)b * NN + q0 + t) * 8));
    {
        const uint32_t st0 = sb + SM_ST;
        if (t < 128)
            CP_ASYNC16(st0 + (uint32_t)t * 16u, (const char*)(g_Kh + ((size_t)b * NN + t) * 8));
#pragma unroll
        for (int i = 0; i < 4; i++) {
            int cid = t + i * 256;
            int vk = cid >> 3, vc = cid & 7;
            CP_ASYNC16(st0 + 2048u + swz128((uint32_t)vk * 128u + (uint32_t)vc * 16u),
                       (const char*)(g_Vh + ((size_t)b * NN + vk) * 64 + vc * 8));
        }
    }
    CP_COMMIT();
    {
        const uint32_t st1 = sb + SM_ST + STAGE;
        if (t < 128)
            CP_ASYNC16(st1 + (uint32_t)t * 16u, (const char*)(g_Kh + ((size_t)b * NN + 128 + t) * 8));
#pragma unroll
        for (int i = 0; i < 4; i++) {
            int cid = t + i * 256;
            int vk = cid >> 3, vc = cid & 7;
            CP_ASYNC16(st1 + 2048u + swz128((uint32_t)vk * 128u + (uint32_t)vc * 16u),
                       (const char*)(g_Vh + ((size_t)b * NN + 128 + vk) * 64 + vc * 8));
        }
    }
    CP_COMMIT();

    uint32_t o[2][16];                          // [rowfrag][nt*2+d] f16x2 accumulators
#pragma unroll
    for (int rf = 0; rf < 2; rf++)
#pragma unroll
        for (int i = 0; i < 16; i++) o[rf][i] = 0u;
    float lacc[4] = {0.f, 0.f, 0.f, 0.f};       // row sums: [rf*2+d]
    uint32_t qa[4];
    bool qloaded = false;

    for (int it = 0; it < 32; it++) {
        if (it == 31) { CP_WAIT0(); } else { CP_WAIT1(); }   // tile `it` landed
        __syncthreads();   // all warps done with tile it-1 -> its buffer reusable

        if (it + 2 < 32) {  // prefetch tile it+2 into stage (it+2)%3
            const uint32_t std_ = sb + SM_ST + (uint32_t)((it + 2) % 3) * STAGE;
            const int kbase = (it + 2) * 128;
            if (t < 128)
                CP_ASYNC16(std_ + (uint32_t)t * 16u,
                           (const char*)(g_Kh + ((size_t)b * NN + kbase + t) * 8));
#pragma unroll
            for (int i = 0; i < 4; i++) {
                int cid = t + i * 256;
                int vk = cid >> 3, vc = cid & 7;
                CP_ASYNC16(std_ + 2048u + swz128((uint32_t)vk * 128u + (uint32_t)vc * 16u),
                           (const char*)(g_Vh + ((size_t)b * NN + kbase + vk) * 64 + vc * 8));
            }
            CP_COMMIT();
        }

        if (!qloaded) {  // Q A-frags, resident for whole loop
            LDSM_X4(qa[0], qa[1], qa[2], qa[3], sbQ + (uint32_t)(rowgrp * 32 + lane) * 16u);
            qloaded = true;
        }

        const uint32_t kbuf = sb + SM_ST + (uint32_t)(it % 3) * STAGE;
        const uint32_t vbuf = kbuf + 2048u;

        uint32_t kb[4];     // this warp's 32-key quarter
        LDSM_X4(kb[0], kb[1], kb[2], kb[3], kbuf + (uint32_t)(kq * 32 + lane) * 16u);

        // ---- issue ALL MMA1s up front (both 16-key chunks) ----
        uint32_t sA[8], sB[8];
        mma16808h(sA + 0, qa[0], qa[1], kb[0]);
        mma16808h(sA + 2, qa[0], qa[1], kb[1]);
        mma16808h(sA + 4, qa[2], qa[3], kb[0]);
        mma16808h(sA + 6, qa[2], qa[3], kb[1]);
        mma16808h(sB + 0, qa[0], qa[1], kb[2]);
        mma16808h(sB + 2, qa[0], qa[1], kb[3]);
        mma16808h(sB + 4, qa[2], qa[3], kb[2]);
        mma16808h(sB + 6, qa[2], qa[3], kb[3]);

        // ---- chunk A: EX2 (overlaps MMA1(B)) -> LDSM V -> MMA2 ----
        EX2H2(sA[0]); EX2H2(sA[1]); EX2H2(sA[2]); EX2H2(sA[3]);
        EX2H2(sA[4]); EX2H2(sA[5]); EX2H2(sA[6]); EX2H2(sA[7]);
        {
            uint32_t vb[16];
            const uint32_t vkey = (uint32_t)(kq * 32 + ((lane >> 3) & 1) * 8 + (lane & 7));
#pragma unroll
            for (int ntp = 0; ntp < 4; ntp++) {
                uint32_t cb = (uint32_t)(ntp * 2 + (lane >> 4));
                LDSM_X4T(vb[4 * ntp], vb[4 * ntp + 1], vb[4 * ntp + 2], vb[4 * ntp + 3],
                         vbuf + swz128(vkey * 128u + cb * 16u));
            }
#pragma unroll
            for (int nt = 0; nt < 8; nt++) {
                mma16816h(&o[0][2 * nt], sA + 0, vb[2 * nt], vb[2 * nt + 1]);
                mma16816h(&o[1][2 * nt], sA + 4, vb[2 * nt], vb[2 * nt + 1]);
            }
        }

        // ---- chunk B: EX2 (overlaps MMA2(A)) -> LDSM V -> MMA2 ----
        EX2H2(sB[0]); EX2H2(sB[1]); EX2H2(sB[2]); EX2H2(sB[3]);
        EX2H2(sB[4]); EX2H2(sB[5]); EX2H2(sB[6]); EX2H2(sB[7]);
        {
            uint32_t vb[16];
            const uint32_t vkey = (uint32_t)(kq * 32 + 16 + ((lane >> 3) & 1) * 8 + (lane & 7));
#pragma unroll
            for (int ntp = 0; ntp < 4; ntp++) {
                uint32_t cb = (uint32_t)(ntp * 2 + (lane >> 4));
                LDSM_X4T(vb[4 * ntp], vb[4 * ntp + 1], vb[4 * ntp + 2], vb[4 * ntp + 3],
                         vbuf + swz128(vkey * 128u + cb * 16u));
            }
#pragma unroll
            for (int nt = 0; nt < 8; nt++) {
                mma16816h(&o[0][2 * nt], sB + 0, vb[2 * nt], vb[2 * nt + 1]);
                mma16816h(&o[1][2 * nt], sB + 4, vb[2 * nt], vb[2 * nt + 1]);
            }
        }

        // ---- row sums (off critical path) ----
        lacc[0] += h2sumf(hadd2u(sA[0], sA[2])) + h2sumf(hadd2u(sB[0], sB[2]));
        lacc[1] += h2sumf(hadd2u(sA[1], sA[3])) + h2sumf(hadd2u(sB[1], sB[3]));
        lacc[2] += h2sumf(hadd2u(sA[4], sA[6])) + h2sumf(hadd2u(sB[4], sB[6]));
        lacc[3] += h2sumf(hadd2u(sA[5], sA[7])) + h2sumf(hadd2u(sB[5], sB[7]));
    }

    // ---- epilogue: combine 4 key-quarters through smem ----
#pragma unroll
    for (int j = 0; j < 4; j++) {
        lacc[j] += __shfl_xor_sync(0xffffffffu, lacc[j], 1);
        lacc[j] += __shfl_xor_sync(0xffffffffu, lacc[j], 2);
    }
    const float gma = __ldg(gamma_p);

    __syncthreads();            // all loop reads of stages done -> reuse region

    __half* sOp = (__half*)(dynsm + EP_OP);     // [kq][ch 64][q 64] f16 partials
    float*  sL  = (float*)(dynsm + EP_L);       // [kq][64] partial row sums

    if ((lane & 3) == 0) {
#pragma unroll
        for (int j = 0; j < 4; j++) {           // j = rf*2+d -> row rf*16 + d*8
            int row = rowgrp * 32 + (j >> 1) * 16 + (j & 1) * 8 + (lane >> 2);
            sL[kq * 64 + row] = lacc[j];
        }
    }
#pragma unroll
    for (int rf = 0; rf < 2; rf++)
#pragma unroll
        for (int nt = 0; nt < 8; nt++)
#pragma unroll
            for (int d = 0; d < 2; d++) {
                __half2 hv = *reinterpret_cast<__half2*>(&o[rf][nt * 2 + d]);
                int row = rowgrp * 32 + rf * 16 + d * 8 + (lane >> 2);
                int c0  = nt * 8 + (lane & 3) * 2;
                sOp[(kq * 64 + c0) * 64 + row]     = __low2half(hv);
                sOp[(kq * 64 + c0 + 1) * 64 + row] = __high2half(hv);
            }
    __syncthreads();

    // final: thread owns q = t&63, channels (t>>6) + 4*i
    {
        const int q = t & 63;
        const float l = sL[q] + sL[64 + q] + sL[128 + q] + sL[192 + q];
        const float inv = gma / l;
#pragma unroll
        for (int i = 0; i < 16; i++) {
            int c = (t >> 6) + 4 * i;
            float acc = (float)sOp[(0 * 64 + c) * 64 + q] + (float)sOp[(1 * 64 + c) * 64 + q]
                      + (float)sOp[(2 * 64 + c) * 64 + q] + (float)sOp[(3 * 64 + c) * 64 + q];
            size_t idx = ((size_t)b * 64 + c) * NN + q0 + q;
            out[idx] = acc * inv + x[idx];
        }
    }
}

// ---------------------------------------------------------------------------
extern "C" void kernel_launch(void* const* d_in, const int* in_sizes, int n_in,
                              void* d_out, int out_size) {
    (void)in_sizes; (void)n_in; (void)out_size;
    const float* x     = (const float*)d_in[0];
    const float* Wq    = (const float*)d_in[1];
    const float* bq    = (const float*)d_in[2];
    const float* Wk    = (const float*)d_in[3];
    const float* bk    = (const float*)d_in[4];
    const float* Wv    = (const float*)d_in[5];
    const float* bv    = (const float*)d_in[6];
    const float* gamma = (const float*)d_in[7];
    float* out = (float*)d_out;

    cudaFuncSetAttribute(attn_kernel, cudaFuncAttributeMaxDynamicSharedMemorySize,
                         (int)DSMEM_BYTES);

    prep_kernel<<<dim3(64, NB), 256>>>(x, Wq, bq, Wk, bk, Wv, bv);

    // attn with programmatic stream serialization
    cudaLaunchConfig_t cfg = {};
    cfg.gridDim  = dim3(64, NB);
    cfg.blockDim = dim3(256);
    cfg.dynamicSmemBytes = DSMEM_BYTES;
    cfg.stream = 0;
    cudaLaunchAttribute attrs[1];
    attrs[0].id = cudaLaunchAttributeProgrammaticStreamSerialization;
    attrs[0].val.programmaticStreamSerializationAllowed = 1;
    cfg.attrs = attrs;
    cfg.numAttrs = 1;
    cudaLaunchKernelEx(&cfg, attn_kernel, x, gamma, out);
}